// round 4
// baseline (speedup 1.0000x reference)
#include <cuda_runtime.h>
#include <cuda_fp16.h>
#include <cstdint>

#define B_     8
#define N_     4096
#define D_     1024
#define EMB_   64
#define CLN_   10
#define TILE_M 64
#define KC_    64                  // k-chunk (fp16 -> 128B rows)
#define NCHUNK (D_ / KC_)          // 16
#define NTHR   128
#define NCTA_X (N_ / TILE_M)       // 64 CTAs per batch
#define PSTRIDE 656                // per-CTA partial row stride (floats, 16B aligned)

// ---------------- device scratch (allocation-free rule) ----------------
// per-CTA partials: [batch][cta][0..639]=cluster sums, [640..649]=counts
__device__ float g_part[B_ * NCTA_X * PSTRIDE];

// ---------------- dynamic smem layout (bytes) ----------------
#define SM_B1S   0                 // 64 f
#define SM_LABS  256               // 64 int
#define SM_CSUM  512               // 2 x 640 f = 5120B -> ends 5632
#define SM_BUF   8192              // 1024-aligned
#define AHI_OFF  0                 // 64 x 128B = 8KB
#define ALO_OFF  8192
#define BH_OFF   16384
#define BUF_BYTES 24576
#define SMEM_TOTAL (SM_BUF + 2 * BUF_BYTES)   // 57344 -> 4 CTAs/SM

__device__ __forceinline__ uint32_t smem_u32(const void* p) {
    uint32_t a;
    asm("{ .reg .u64 t; cvta.to.shared.u64 t, %1; cvt.u32.u64 %0, t; }" : "=r"(a) : "l"(p));
    return a;
}
__device__ __forceinline__ uint32_t sw128(uint32_t o) { return o ^ ((o >> 3) & 0x70); }

__device__ __forceinline__ void ldmx4(uint32_t* r, uint32_t addr) {
    asm volatile("ldmatrix.sync.aligned.m8n8.x4.shared.b16 {%0,%1,%2,%3}, [%4];"
                 : "=r"(r[0]), "=r"(r[1]), "=r"(r[2]), "=r"(r[3]) : "r"(addr));
}
__device__ __forceinline__ void mma16816(float* c, const uint32_t* a, uint32_t b0, uint32_t b1) {
    asm volatile("mma.sync.aligned.m16n8k16.row.col.f32.f16.f16.f32 "
                 "{%0,%1,%2,%3}, {%4,%5,%6,%7}, {%8,%9}, {%0,%1,%2,%3};"
                 : "+f"(c[0]), "+f"(c[1]), "+f"(c[2]), "+f"(c[3])
                 : "r"(a[0]), "r"(a[1]), "r"(a[2]), "r"(a[3]), "r"(b0), "r"(b1));
}

// ---------------------------------------------------------------------------
// Kernel 1: 2-term fp16-split mma.sync GEMM (+bias+ReLU) + per-cluster
// partial reduction. D = (Ahi + Alo) * Bhi ; B converted from fp32 in-kernel.
// CTA: 64 patches x EMB=64, K=1024 in 16 chunks, double-buffered smem.
// ---------------------------------------------------------------------------
__global__ void __launch_bounds__(NTHR)
embed_kernel(const float* __restrict__ data,
             const int*   __restrict__ labels,
             const float* __restrict__ W1,
             const float* __restrict__ b1) {
    extern __shared__ char smem[];
    const uint32_t sb = smem_u32(smem);
    const int tid  = threadIdx.x;
    const int warp = tid >> 5;
    const int lane = tid & 31;
    const int b    = blockIdx.y;
    const int bx   = blockIdx.x;
    const int p0   = bx * TILE_M;

    float* b1s  = (float*)(smem + SM_B1S);
    int*   labs = (int*)  (smem + SM_LABS);
    float* csum = (float*)(smem + SM_CSUM);    // two halves of 640

    if (tid < EMB_)   b1s[tid]  = b1[tid];
    if (tid < TILE_M) labs[tid] = labels[b * N_ + p0 + tid];
    for (int i = tid; i < 2 * CLN_ * EMB_; i += NTHR) csum[i] = 0.0f;

    const float* dbase = data + (size_t)(b * N_ + p0) * D_;

    const int ar = tid >> 4;          // A fill row (per float4 slot)
    const int aq = tid & 15;
    const int we = tid >> 1;          // B fill: embedding row
    const int wk = (tid & 1) * 32;    // B fill: k offset (32 floats)

    // ---- helpers to fill a buffer for chunk kc ----
    auto fillA = [&](char* buf, int kc) {
#pragma unroll
        for (int l = 0; l < 8; l++) {
            int r = ar + l * 8;
            float4 v = *(const float4*)(dbase + (size_t)r * D_ + kc + aq * 4);
            __half2 h0 = __floats2half2_rn(v.x, v.y);
            __half2 h1 = __floats2half2_rn(v.z, v.w);
            float2 f0 = __half22float2(h0), f1 = __half22float2(h1);
            __half2 l0 = __floats2half2_rn(v.x - f0.x, v.y - f0.y);
            __half2 l1 = __floats2half2_rn(v.z - f1.x, v.w - f1.y);
            uint32_t sw = sw128((uint32_t)(r * 128 + aq * 8));
            uint2 hv, lv;
            hv.x = *(uint32_t*)&h0; hv.y = *(uint32_t*)&h1;
            lv.x = *(uint32_t*)&l0; lv.y = *(uint32_t*)&l1;
            *(uint2*)(buf + AHI_OFF + sw) = hv;
            *(uint2*)(buf + ALO_OFF + sw) = lv;
        }
    };
    auto fillB = [&](char* buf, int kc) {
#pragma unroll
        for (int q = 0; q < 8; q++) {
            float4 v = *(const float4*)(W1 + (size_t)we * D_ + kc + wk + q * 4);
            __half2 h0 = __floats2half2_rn(v.x, v.y);
            __half2 h1 = __floats2half2_rn(v.z, v.w);
            uint32_t sw = sw128((uint32_t)(we * 128 + (wk + q * 4) * 2));
            uint2 hv;
            hv.x = *(uint32_t*)&h0; hv.y = *(uint32_t*)&h1;
            *(uint2*)(buf + BH_OFF + sw) = hv;
        }
    };

    // ---- prologue: fill chunk 0 into buf 0 ----
    fillA(smem + SM_BUF, 0);
    fillB(smem + SM_BUF, 0);
    __syncthreads();

    float acc[8][4];
#pragma unroll
    for (int nt = 0; nt < 8; nt++)
#pragma unroll
        for (int i = 0; i < 4; i++) acc[nt][i] = 0.0f;

    const uint32_t arow  = (uint32_t)(warp * 16 + (lane & 15));
    const uint32_t acolb = (uint32_t)((lane >> 4) * 16);
    const uint32_t brow8 = (uint32_t)(((lane >> 4) & 1) * 8 + (lane & 7));
    const uint32_t bkb   = (uint32_t)(((lane >> 3) & 1) * 16);

    for (int c = 0; c < NCHUNK; c++) {
        const int bi = c & 1;
        const uint32_t bufa = sb + SM_BUF + bi * BUF_BYTES;
        char* nbuf = smem + SM_BUF + (bi ^ 1) * BUF_BYTES;

        // ---- prefetch next chunk's A into regs (LDG overlaps MMA) ----
        float4 pre[8];
        if (c + 1 < NCHUNK) {
            const int kc = (c + 1) * KC_;
#pragma unroll
            for (int l = 0; l < 8; l++)
                pre[l] = *(const float4*)(dbase + (size_t)(ar + l * 8) * D_ + kc + aq * 4);
        }

        // ---- MMA over current chunk: 4 k16 steps ----
#pragma unroll
        for (int ks = 0; ks < 4; ks++) {
            uint32_t ah[4], al[4];
            uint32_t aoff = sw128(arow * 128 + (uint32_t)(ks * 32) + acolb);
            ldmx4(ah, bufa + AHI_OFF + aoff);
            ldmx4(al, bufa + ALO_OFF + aoff);
#pragma unroll
            for (int j = 0; j < 4; j++) {
                uint32_t bh[4];
                uint32_t boff = sw128((uint32_t)(j * 16) * 128 + brow8 * 128 +
                                      (uint32_t)(ks * 32) + bkb);
                ldmx4(bh, bufa + BH_OFF + boff);
                mma16816(acc[2 * j],     ah, bh[0], bh[1]);
                mma16816(acc[2 * j],     al, bh[0], bh[1]);
                mma16816(acc[2 * j + 1], ah, bh[2], bh[3]);
                mma16816(acc[2 * j + 1], al, bh[2], bh[3]);
            }
        }

        // ---- convert + store next chunk ----
        if (c + 1 < NCHUNK) {
            const int kc = (c + 1) * KC_;
#pragma unroll
            for (int l = 0; l < 8; l++) {
                int r = ar + l * 8;
                float4 v = pre[l];
                __half2 h0 = __floats2half2_rn(v.x, v.y);
                __half2 h1 = __floats2half2_rn(v.z, v.w);
                float2 f0 = __half22float2(h0), f1 = __half22float2(h1);
                __half2 l0 = __floats2half2_rn(v.x - f0.x, v.y - f0.y);
                __half2 l1 = __floats2half2_rn(v.z - f1.x, v.w - f1.y);
                uint32_t sw = sw128((uint32_t)(r * 128 + aq * 8));
                uint2 hv, lv;
                hv.x = *(uint32_t*)&h0; hv.y = *(uint32_t*)&h1;
                lv.x = *(uint32_t*)&l0; lv.y = *(uint32_t*)&l1;
                *(uint2*)(nbuf + AHI_OFF + sw) = hv;
                *(uint2*)(nbuf + ALO_OFF + sw) = lv;
            }
            fillB(nbuf, kc);
        }
        __syncthreads();
    }

    // ---- epilogue: bias + ReLU -> smem e-tile, split-row reduction ----
    float* etile = (float*)(smem + SM_BUF);     // 64 x 66 floats (buf region free)
    {
        int r0 = warp * 16 + (lane >> 2);
        int cq = 2 * (lane & 3);
#pragma unroll
        for (int nt = 0; nt < 8; nt++) {
            int col = nt * 8 + cq;
            float bv0 = b1s[col], bv1 = b1s[col + 1];
            etile[r0 * 66 + col]           = fmaxf(acc[nt][0] + bv0, 0.0f);
            etile[r0 * 66 + col + 1]       = fmaxf(acc[nt][1] + bv1, 0.0f);
            etile[(r0 + 8) * 66 + col]     = fmaxf(acc[nt][2] + bv0, 0.0f);
            etile[(r0 + 8) * 66 + col + 1] = fmaxf(acc[nt][3] + bv1, 0.0f);
        }
    }
    __syncthreads();

    // threads 0-63: rows 0..31 -> csum[0]; threads 64-127: rows 32..63 -> csum[1]
    {
        int half = tid >> 6;             // 0 or 1
        int e    = tid & 63;
        float* cs = csum + half * (CLN_ * EMB_);
        int rbase = half * 32;
        for (int r = 0; r < 32; r++) {
            int row = rbase + r;
            cs[labs[row] * EMB_ + e] += etile[row * 66 + e];
        }
    }
    __syncthreads();

    float* prow = g_part + ((size_t)b * NCTA_X + bx) * PSTRIDE;
    for (int i = tid; i < CLN_ * EMB_; i += NTHR)
        prow[i] = csum[i] + csum[CLN_ * EMB_ + i];
    if (tid < CLN_) {
        int cnt = 0;
        for (int r = 0; r < TILE_M; r++) cnt += (labs[r] == tid);
        prow[640 + tid] = (float)cnt;
    }
}

// ---------------------------------------------------------------------------
// Kernel 2: reduce per-CTA partials + attention head + masked softmax + fc6.
// One block (256 threads) per batch.
// ---------------------------------------------------------------------------
__global__ void head_kernel(const float* __restrict__ Wa1, const float* __restrict__ ba1,
                            const float* __restrict__ Wa2, const float* __restrict__ ba2,
                            const float* __restrict__ Wf1, const float* __restrict__ bf1,
                            const float* __restrict__ Wf2, const float* __restrict__ bf2,
                            float* __restrict__ out) {
    __shared__ float hc[650];
    __shared__ float h[CLN_][EMB_];
    __shared__ float u[CLN_][32];
    __shared__ float score[CLN_], Avec[CLN_], mask[CLN_];
    __shared__ float Mv[EMB_], f[32];

    const int b   = blockIdx.x;
    const int tid = threadIdx.x;   // 256 threads

    // phase 1: reduce 64 CTA partials (coalesced across tid)
    for (int i = tid; i < 650; i += 256) {
        float s = 0.0f;
        const float* base = g_part + (size_t)b * NCTA_X * PSTRIDE + i;
#pragma unroll 8
        for (int j = 0; j < NCTA_X; j++) s += base[j * PSTRIDE];
        hc[i] = s;
    }
    __syncthreads();

    if (tid < EMB_) {
        for (int c = 0; c < CLN_; c++) {
            float cnt = hc[640 + c];
            h[c][tid] = hc[c * EMB_ + tid] / fmaxf(cnt, 1.0f);
        }
    }
    if (tid < CLN_) mask[tid] = (hc[640 + tid] > 0.0f) ? 1.0f : 0.0f;
    __syncthreads();

    if (tid < 32) {
        for (int c = 0; c < CLN_; c++) {
            float s = ba1[tid];
            for (int e = 0; e < EMB_; e++) s += h[c][e] * Wa1[tid * EMB_ + e];
            u[c][tid] = tanhf(s);
        }
    }
    __syncthreads();

    if (tid < CLN_) {
        float s = ba2[0];
        for (int k = 0; k < 32; k++) s += u[tid][k] * Wa2[k];
        score[tid] = s;
    }
    __syncthreads();

    if (tid == 0) {
        float xmax = -1e30f;
        for (int c = 0; c < CLN_; c++) {
            float xm = score[c] * mask[c] + (1.0f - 1.0f / (mask[c] + 1e-5f));
            xmax = fmaxf(xmax, xm);
        }
        float ssum = 0.0f;
        for (int c = 0; c < CLN_; c++) {
            float ex = expf(score[c] - xmax) * mask[c];
            Avec[c] = ex;
            ssum += ex;
        }
        for (int c = 0; c < CLN_; c++) Avec[c] /= ssum;
    }
    __syncthreads();

    if (tid < EMB_) {
        float m = 0.0f;
        for (int c = 0; c < CLN_; c++) m += Avec[c] * h[c][tid];
        Mv[tid] = m;
    }
    __syncthreads();

    if (tid < 32) {
        float s = bf1[tid];
        for (int e = 0; e < EMB_; e++) s += Mv[e] * Wf1[tid * EMB_ + e];
        f[tid] = fmaxf(s, 0.0f);
    }
    __syncthreads();

    if (tid == 0) {
        float s = bf2[0];
        for (int k = 0; k < 32; k++) s += f[k] * Wf2[k];
        out[b] = s;
    }
}

// ---------------------------------------------------------------------------
extern "C" void kernel_launch(void* const* d_in, const int* in_sizes, int n_in,
                              void* d_out, int out_size) {
    const float* data   = (const float*)d_in[0];
    const int*   labels = (const int*)  d_in[1];
    const float* W1     = (const float*)d_in[2];
    const float* b1     = (const float*)d_in[3];
    const float* Wa1    = (const float*)d_in[4];
    const float* ba1    = (const float*)d_in[5];
    const float* Wa2    = (const float*)d_in[6];
    const float* ba2    = (const float*)d_in[7];
    const float* Wf1    = (const float*)d_in[8];
    const float* bf1    = (const float*)d_in[9];
    const float* Wf2    = (const float*)d_in[10];
    const float* bf2    = (const float*)d_in[11];

    cudaFuncSetAttribute(embed_kernel, cudaFuncAttributeMaxDynamicSharedMemorySize,
                         SMEM_TOTAL);

    embed_kernel<<<dim3(NCTA_X, B_), NTHR, SMEM_TOTAL>>>(data, labels, W1, b1);
    head_kernel<<<B_, 256>>>(Wa1, ba1, Wa2, ba2, Wf1, bf1, Wf2, bf2, (float*)d_out);
}

// round 5
// speedup vs baseline: 1.0438x; 1.0438x over previous
#include <cuda_runtime.h>
#include <cuda_fp16.h>
#include <cstdint>

#define B_     8
#define N_     4096
#define D_     1024
#define EMB_   64
#define CLN_   10
#define TILE_M 128
#define KC_    64                  // k-chunk (fp16 -> 128B rows)
#define NCHUNK (D_ / KC_)          // 16
#define NTHR   256
#define NCTA_X (N_ / TILE_M)       // 32 CTAs per batch
#define PSTRIDE 656

// ---------------- device scratch (allocation-free rule) ----------------
__device__ float g_part[B_ * NCTA_X * PSTRIDE];
__device__ int   g_done[B_];        // zero-init; reset by head CTA each call

// ---------------- dynamic smem layout (bytes) ----------------
#define SM_B1S   0                 // 64 f
#define SM_LABS  256               // 128 int -> 768
#define SM_CSUM  1024              // 4 x 640 f = 10240 -> 11264
#define SM_BUF   12288             // 1024-aligned
#define AHI_OFF  0                 // 128 x 128B = 16KB
#define ALO_OFF  16384
#define BHI_OFF  32768             // 64 x 128B = 8KB
#define BLO_OFF  40960
#define BUF_BYTES 49152
#define SMEM_TOTAL (SM_BUF + 2 * BUF_BYTES)   // 110592 -> 2 CTAs/SM

__device__ __forceinline__ uint32_t smem_u32(const void* p) {
    uint32_t a;
    asm("{ .reg .u64 t; cvta.to.shared.u64 t, %1; cvt.u32.u64 %0, t; }" : "=r"(a) : "l"(p));
    return a;
}
__device__ __forceinline__ uint32_t sw128(uint32_t o) { return o ^ ((o >> 3) & 0x70); }

__device__ __forceinline__ void ldmx4(uint32_t* r, uint32_t addr) {
    asm volatile("ldmatrix.sync.aligned.m8n8.x4.shared.b16 {%0,%1,%2,%3}, [%4];"
                 : "=r"(r[0]), "=r"(r[1]), "=r"(r[2]), "=r"(r[3]) : "r"(addr));
}
__device__ __forceinline__ void mma16816(float* c, const uint32_t* a, uint32_t b0, uint32_t b1) {
    asm volatile("mma.sync.aligned.m16n8k16.row.col.f32.f16.f16.f32 "
                 "{%0,%1,%2,%3}, {%4,%5,%6,%7}, {%8,%9}, {%0,%1,%2,%3};"
                 : "+f"(c[0]), "+f"(c[1]), "+f"(c[2]), "+f"(c[3])
                 : "r"(a[0]), "r"(a[1]), "r"(a[2]), "r"(a[3]), "r"(b0), "r"(b1));
}

// ---------------------------------------------------------------------------
// Fused kernel: 3-term fp16-split mma.sync GEMM (+bias+ReLU) + per-cluster
// partial reduction; the LAST CTA of each batch reduces partials and runs the
// attention head + masked softmax + fc6, writing out[b].
// ---------------------------------------------------------------------------
__global__ void __launch_bounds__(NTHR, 2)
fused_kernel(const float* __restrict__ data,
             const int*   __restrict__ labels,
             const float* __restrict__ W1,
             const float* __restrict__ b1,
             const float* __restrict__ Wa1, const float* __restrict__ ba1,
             const float* __restrict__ Wa2, const float* __restrict__ ba2,
             const float* __restrict__ Wf1, const float* __restrict__ bf1,
             const float* __restrict__ Wf2, const float* __restrict__ bf2,
             float* __restrict__ out) {
    extern __shared__ char smem[];
    const uint32_t sb = smem_u32(smem);
    const int tid  = threadIdx.x;
    const int warp = tid >> 5;
    const int lane = tid & 31;
    const int b    = blockIdx.y;
    const int bx   = blockIdx.x;
    const int p0   = bx * TILE_M;

    float* b1s  = (float*)(smem + SM_B1S);
    int*   labs = (int*)  (smem + SM_LABS);
    float* csum = (float*)(smem + SM_CSUM);    // 4 copies of 640

    if (tid < EMB_) b1s[tid] = b1[tid];
    if (tid < TILE_M) labs[tid] = labels[b * N_ + p0 + tid];
    for (int i = tid; i < 4 * CLN_ * EMB_; i += NTHR) csum[i] = 0.0f;

    const float* dbase = data + (size_t)(b * N_ + p0) * D_;

    const int ar = tid >> 4;          // A fill row (per float4 slot), 0..15
    const int aq = tid & 15;
    const int we = tid >> 2;          // B fill row, 0..63
    const int wq = tid & 3;

    auto cvtStoreA = [&](char* buf, const float4* v) {
#pragma unroll
        for (int l = 0; l < 8; l++) {
            int r = ar + l * 16;
            float4 x = v[l];
            __half2 h0 = __floats2half2_rn(x.x, x.y);
            __half2 h1 = __floats2half2_rn(x.z, x.w);
            float2 f0 = __half22float2(h0), f1 = __half22float2(h1);
            __half2 l0 = __floats2half2_rn(x.x - f0.x, x.y - f0.y);
            __half2 l1 = __floats2half2_rn(x.z - f1.x, x.w - f1.y);
            uint32_t sw = sw128((uint32_t)(r * 128 + aq * 8));
            uint2 hv, lv;
            hv.x = *(uint32_t*)&h0; hv.y = *(uint32_t*)&h1;
            lv.x = *(uint32_t*)&l0; lv.y = *(uint32_t*)&l1;
            *(uint2*)(buf + AHI_OFF + sw) = hv;
            *(uint2*)(buf + ALO_OFF + sw) = lv;
        }
    };
    auto fillB = [&](char* buf, int kc) {
#pragma unroll
        for (int m = 0; m < 4; m++) {
            int kq = wq + m * 4;           // float4 index within row
            float4 v = *(const float4*)(W1 + (size_t)we * D_ + kc + kq * 4);
            __half2 h0 = __floats2half2_rn(v.x, v.y);
            __half2 h1 = __floats2half2_rn(v.z, v.w);
            float2 f0 = __half22float2(h0), f1 = __half22float2(h1);
            __half2 l0 = __floats2half2_rn(v.x - f0.x, v.y - f0.y);
            __half2 l1 = __floats2half2_rn(v.z - f1.x, v.w - f1.y);
            uint32_t sw = sw128((uint32_t)(we * 128 + kq * 8));
            uint2 hv, lv;
            hv.x = *(uint32_t*)&h0; hv.y = *(uint32_t*)&h1;
            lv.x = *(uint32_t*)&l0; lv.y = *(uint32_t*)&l1;
            *(uint2*)(buf + BHI_OFF + sw) = hv;
            *(uint2*)(buf + BLO_OFF + sw) = lv;
        }
    };

    // ---- prologue: chunk 0 into buf 0 ----
    {
        float4 v[8];
#pragma unroll
        for (int l = 0; l < 8; l++)
            v[l] = *(const float4*)(dbase + (size_t)(ar + l * 16) * D_ + aq * 4);
        cvtStoreA(smem + SM_BUF, v);
        fillB(smem + SM_BUF, 0);
    }
    __syncthreads();

    float acc[8][4];
#pragma unroll
    for (int nt = 0; nt < 8; nt++)
#pragma unroll
        for (int i = 0; i < 4; i++) acc[nt][i] = 0.0f;

    const uint32_t arow  = (uint32_t)(warp * 16 + (lane & 15));
    const uint32_t acolb = (uint32_t)((lane >> 4) * 16);
    const uint32_t brow8 = (uint32_t)(((lane >> 4) & 1) * 8 + (lane & 7));
    const uint32_t bkb   = (uint32_t)(((lane >> 3) & 1) * 16);

    for (int c = 0; c < NCHUNK; c++) {
        const int bi = c & 1;
        const uint32_t bufa = sb + SM_BUF + bi * BUF_BYTES;
        char* nbuf = smem + SM_BUF + (bi ^ 1) * BUF_BYTES;

        // prefetch next A chunk into regs (LDG latency covered by MMA phase)
        float4 pre[8];
        if (c + 1 < NCHUNK) {
            const int kc = (c + 1) * KC_;
#pragma unroll
            for (int l = 0; l < 8; l++)
                pre[l] = *(const float4*)(dbase + (size_t)(ar + l * 16) * D_ + kc + aq * 4);
        }

        // MMA over current chunk: 4 k16 steps, 3-term split
#pragma unroll
        for (int ks = 0; ks < 4; ks++) {
            uint32_t ah[4], al[4];
            uint32_t aoff = sw128(arow * 128 + (uint32_t)(ks * 32) + acolb);
            ldmx4(ah, bufa + AHI_OFF + aoff);
            ldmx4(al, bufa + ALO_OFF + aoff);
#pragma unroll
            for (int j = 0; j < 4; j++) {
                uint32_t bh[4], bl[4];
                uint32_t boff = sw128((uint32_t)(j * 16 + (int)brow8) * 128 +
                                      (uint32_t)(ks * 32) + bkb);
                ldmx4(bh, bufa + BHI_OFF + boff);
                ldmx4(bl, bufa + BLO_OFF + boff);
                mma16816(acc[2 * j],     ah, bh[0], bh[1]);
                mma16816(acc[2 * j],     ah, bl[0], bl[1]);
                mma16816(acc[2 * j],     al, bh[0], bh[1]);
                mma16816(acc[2 * j + 1], ah, bh[2], bh[3]);
                mma16816(acc[2 * j + 1], ah, bl[2], bl[3]);
                mma16816(acc[2 * j + 1], al, bh[2], bh[3]);
            }
        }

        if (c + 1 < NCHUNK) {
            cvtStoreA(nbuf, pre);
            fillB(nbuf, (c + 1) * KC_);
        }
        __syncthreads();
    }

    // ---- epilogue: bias + ReLU -> smem e-tile (128 x 66), 4-way reduction ----
    float* etile = (float*)(smem + SM_BUF);
    {
        int r0 = warp * 16 + (lane >> 2);
        int cq = 2 * (lane & 3);
#pragma unroll
        for (int nt = 0; nt < 8; nt++) {
            int col = nt * 8 + cq;
            float bv0 = b1s[col], bv1 = b1s[col + 1];
            etile[r0 * 66 + col]           = fmaxf(acc[nt][0] + bv0, 0.0f);
            etile[r0 * 66 + col + 1]       = fmaxf(acc[nt][1] + bv1, 0.0f);
            etile[(r0 + 8) * 66 + col]     = fmaxf(acc[nt][2] + bv0, 0.0f);
            etile[(r0 + 8) * 66 + col + 1] = fmaxf(acc[nt][3] + bv1, 0.0f);
        }
    }
    __syncthreads();

    {
        int quarter = tid >> 6;          // 0..3, 32 rows each
        int e       = tid & 63;
        float* cs = csum + quarter * (CLN_ * EMB_);
        int rbase = quarter * 32;
        for (int r = 0; r < 32; r++) {
            int row = rbase + r;
            cs[labs[row] * EMB_ + e] += etile[row * 66 + e];
        }
    }
    __syncthreads();

    float* prow = g_part + ((size_t)b * NCTA_X + bx) * PSTRIDE;
    for (int i = tid; i < CLN_ * EMB_; i += NTHR)
        prow[i] = csum[i] + csum[640 + i] + csum[1280 + i] + csum[1920 + i];
    if (tid < CLN_) {
        int cnt = 0;
        for (int r = 0; r < TILE_M; r++) cnt += (labs[r] == tid);
        prow[640 + tid] = (float)cnt;
    }
    __threadfence();
    __syncthreads();

    // ---- last CTA of this batch runs the head ----
    __shared__ int s_last;
    if (tid == 0) s_last = (atomicAdd(&g_done[b], 1) == NCTA_X - 1) ? 1 : 0;
    __syncthreads();
    if (!s_last) return;
    __threadfence();

    __shared__ float hc[650];
    __shared__ float h[CLN_][EMB_];
    __shared__ float u[CLN_][32];
    __shared__ float score[CLN_], Avec[CLN_], mask[CLN_];
    __shared__ float Mv[EMB_], f[32];

    for (int i = tid; i < 650; i += NTHR) {
        float s = 0.0f;
        const float* base = g_part + (size_t)b * NCTA_X * PSTRIDE + i;
#pragma unroll 8
        for (int j = 0; j < NCTA_X; j++) s += base[j * PSTRIDE];
        hc[i] = s;
    }
    __syncthreads();

    if (tid < EMB_) {
        for (int c = 0; c < CLN_; c++)
            h[c][tid] = hc[c * EMB_ + tid] / fmaxf(hc[640 + c], 1.0f);
    }
    if (tid < CLN_) mask[tid] = (hc[640 + tid] > 0.0f) ? 1.0f : 0.0f;
    __syncthreads();

    if (tid < 32) {
        for (int c = 0; c < CLN_; c++) {
            float s = ba1[tid];
            for (int e = 0; e < EMB_; e++) s += h[c][e] * Wa1[tid * EMB_ + e];
            u[c][tid] = tanhf(s);
        }
    }
    __syncthreads();

    if (tid < CLN_) {
        float s = ba2[0];
        for (int k = 0; k < 32; k++) s += u[tid][k] * Wa2[k];
        score[tid] = s;
    }
    __syncthreads();

    if (tid == 0) {
        float xmax = -1e30f;
        for (int c = 0; c < CLN_; c++) {
            float xm = score[c] * mask[c] + (1.0f - 1.0f / (mask[c] + 1e-5f));
            xmax = fmaxf(xmax, xm);
        }
        float ssum = 0.0f;
        for (int c = 0; c < CLN_; c++) {
            float ex = expf(score[c] - xmax) * mask[c];
            Avec[c] = ex;
            ssum += ex;
        }
        for (int c = 0; c < CLN_; c++) Avec[c] /= ssum;
    }
    __syncthreads();

    if (tid < EMB_) {
        float m = 0.0f;
        for (int c = 0; c < CLN_; c++) m += Avec[c] * h[c][tid];
        Mv[tid] = m;
    }
    __syncthreads();

    if (tid < 32) {
        float s = bf1[tid];
        for (int e = 0; e < EMB_; e++) s += Mv[e] * Wf1[tid * EMB_ + e];
        f[tid] = fmaxf(s, 0.0f);
    }
    __syncthreads();

    if (tid == 0) {
        float s = bf2[0];
        for (int k = 0; k < 32; k++) s += f[k] * Wf2[k];
        out[b] = s;
        g_done[b] = 0;      // reset for next graph replay (deterministic)
    }
}

// ---------------------------------------------------------------------------
extern "C" void kernel_launch(void* const* d_in, const int* in_sizes, int n_in,
                              void* d_out, int out_size) {
    const float* data   = (const float*)d_in[0];
    const int*   labels = (const int*)  d_in[1];
    const float* W1     = (const float*)d_in[2];
    const float* b1     = (const float*)d_in[3];
    const float* Wa1    = (const float*)d_in[4];
    const float* ba1    = (const float*)d_in[5];
    const float* Wa2    = (const float*)d_in[6];
    const float* ba2    = (const float*)d_in[7];
    const float* Wf1    = (const float*)d_in[8];
    const float* bf1    = (const float*)d_in[9];
    const float* Wf2    = (const float*)d_in[10];
    const float* bf2    = (const float*)d_in[11];

    cudaFuncSetAttribute(fused_kernel, cudaFuncAttributeMaxDynamicSharedMemorySize,
                         SMEM_TOTAL);

    fused_kernel<<<dim3(NCTA_X, B_), NTHR, SMEM_TOTAL>>>(
        data, labels, W1, b1, Wa1, ba1, Wa2, ba2, Wf1, bf1, Wf2, bf2,
        (float*)d_out);
}

// round 6
// speedup vs baseline: 1.1622x; 1.1134x over previous
#include <cuda_runtime.h>
#include <cuda_fp16.h>
#include <cstdint>

#define B_     8
#define N_     4096
#define D_     1024
#define EMB_   64
#define CLN_   10
#define TILE_M 64
#define KC_    64                  // k-chunk
#define NCHUNK (D_ / KC_)          // 16
#define NTHR   128
#define NCTA_X (N_ / TILE_M)       // 64 CTAs per batch
#define PSTRIDE 656

// ---------------- device scratch (allocation-free rule) ----------------
__device__ float g_part[B_ * NCTA_X * PSTRIDE];
__device__ int   g_done[B_];                      // zero-init; self-resetting
__device__ __align__(16) __half g_W1hi[EMB_ * D_];
__device__ __align__(16) __half g_W1lo[EMB_ * D_];

// ---------------- dynamic smem layout (bytes) ----------------
#define SM_B1S    0                // 64 f
#define SM_LABS   256              // 64 int
#define SM_CSUM   512              // 2 x 640 f = 5120 -> 5632
#define SM_ABUF   6144             // 2 stages x (64 rows x 288B) = 36864
#define A_STAGE   18432
#define A_ROWB    288              // fp32 row: 256B data + 32B pad (bank-clean LDS)
#define SM_BBUF   (SM_ABUF + 2 * A_STAGE)   // 43008
#define B_STAGE   16384            // Bhi 8KB + Blo 8KB
#define BLO_OFF   8192
#define SMEM_TOTAL (SM_BBUF + 2 * B_STAGE)  // 75776 -> 3 CTAs/SM

__device__ __forceinline__ uint32_t smem_u32(const void* p) {
    uint32_t a;
    asm("{ .reg .u64 t; cvta.to.shared.u64 t, %1; cvt.u32.u64 %0, t; }" : "=r"(a) : "l"(p));
    return a;
}
__device__ __forceinline__ uint32_t sw128(uint32_t o) { return o ^ ((o >> 3) & 0x70); }

__device__ __forceinline__ void ldmx4(uint32_t* r, uint32_t addr) {
    asm volatile("ldmatrix.sync.aligned.m8n8.x4.shared.b16 {%0,%1,%2,%3}, [%4];"
                 : "=r"(r[0]), "=r"(r[1]), "=r"(r[2]), "=r"(r[3]) : "r"(addr));
}
__device__ __forceinline__ void mma16816(float* c, const uint32_t* a, uint32_t b0, uint32_t b1) {
    asm volatile("mma.sync.aligned.m16n8k16.row.col.f32.f16.f16.f32 "
                 "{%0,%1,%2,%3}, {%4,%5,%6,%7}, {%8,%9}, {%0,%1,%2,%3};"
                 : "+f"(c[0]), "+f"(c[1]), "+f"(c[2]), "+f"(c[3])
                 : "r"(a[0]), "r"(a[1]), "r"(a[2]), "r"(a[3]), "r"(b0), "r"(b1));
}
__device__ __forceinline__ void cpasync16(uint32_t saddr, const void* gaddr) {
    asm volatile("cp.async.cg.shared.global [%0], [%1], 16;" :: "r"(saddr), "l"(gaddr));
}

// ---------------------------------------------------------------------------
// Kernel 0: split-convert W1 to fp16 hi/lo (vectorized)
// ---------------------------------------------------------------------------
__global__ void init_kernel(const float* __restrict__ W1) {
    int i4 = blockIdx.x * 256 + threadIdx.x;      // float4 index, 0..16383
    float4 v = *(const float4*)(W1 + (size_t)i4 * 4);
    __half2 h0 = __floats2half2_rn(v.x, v.y);
    __half2 h1 = __floats2half2_rn(v.z, v.w);
    float2 f0 = __half22float2(h0), f1 = __half22float2(h1);
    __half2 l0 = __floats2half2_rn(v.x - f0.x, v.y - f0.y);
    __half2 l1 = __floats2half2_rn(v.z - f1.x, v.w - f1.y);
    uint2 hv, lv;
    hv.x = *(uint32_t*)&h0; hv.y = *(uint32_t*)&h1;
    lv.x = *(uint32_t*)&l0; lv.y = *(uint32_t*)&l1;
    *(uint2*)(g_W1hi + (size_t)i4 * 4) = hv;
    *(uint2*)(g_W1lo + (size_t)i4 * 4) = lv;
}

// ---------------------------------------------------------------------------
// Fused kernel: cp.async-fed 3-term fp16-split mma.sync GEMM (+bias+ReLU) +
// per-cluster partials; last CTA per batch runs the attention head.
// A kept fp32 in smem; fragments assembled via LDS + in-register hi/lo cvt.
// ---------------------------------------------------------------------------
__global__ void __launch_bounds__(NTHR)
fused_kernel(const float* __restrict__ data,
             const int*   __restrict__ labels,
             const float* __restrict__ b1,
             const float* __restrict__ Wa1, const float* __restrict__ ba1,
             const float* __restrict__ Wa2, const float* __restrict__ ba2,
             const float* __restrict__ Wf1, const float* __restrict__ bf1,
             const float* __restrict__ Wf2, const float* __restrict__ bf2,
             float* __restrict__ out) {
    extern __shared__ char smem[];
    const uint32_t sb = smem_u32(smem);
    const int tid  = threadIdx.x;
    const int warp = tid >> 5;
    const int lane = tid & 31;
    const int b    = blockIdx.y;
    const int bx   = blockIdx.x;
    const int p0   = bx * TILE_M;

    float* b1s  = (float*)(smem + SM_B1S);
    int*   labs = (int*)  (smem + SM_LABS);
    float* csum = (float*)(smem + SM_CSUM);

    if (tid < EMB_)   b1s[tid]  = b1[tid];
    if (tid < TILE_M) labs[tid] = labels[b * N_ + p0 + tid];
    for (int i = tid; i < 2 * CLN_ * EMB_; i += NTHR) csum[i] = 0.0f;

    const float* dbase = data + (size_t)(b * N_ + p0) * D_;

    // cp.async issue for one chunk into stage si
    auto issueChunk = [&](int si, int kc) {
        const uint32_t abase = sb + SM_ABUF + si * A_STAGE;
        const uint32_t bbase = sb + SM_BBUF + si * B_STAGE;
#pragma unroll
        for (int l = 0; l < 8; l++) {             // A: 64 rows x 256B fp32
            int idx = tid + l * NTHR;
            int r = idx >> 4, kq = idx & 15;
            cpasync16(abase + r * A_ROWB + kq * 16,
                      dbase + (size_t)r * D_ + kc + kq * 4);
        }
#pragma unroll
        for (int l = 0; l < 4; l++) {             // B hi: 64 rows x 128B fp16
            int idx = tid + l * NTHR;
            int r = idx >> 3, kq = idx & 7;
            uint32_t sw = sw128((uint32_t)(r * 128 + kq * 16));
            cpasync16(bbase + sw,           g_W1hi + (size_t)r * D_ + kc + kq * 8);
        }
#pragma unroll
        for (int l = 0; l < 4; l++) {             // B lo
            int idx = tid + l * NTHR;
            int r = idx >> 3, kq = idx & 7;
            uint32_t sw = sw128((uint32_t)(r * 128 + kq * 16));
            cpasync16(bbase + BLO_OFF + sw, g_W1lo + (size_t)r * D_ + kc + kq * 8);
        }
        asm volatile("cp.async.commit_group;");
    };

    issueChunk(0, 0);

    float acc[8][4];
#pragma unroll
    for (int nt = 0; nt < 8; nt++)
#pragma unroll
        for (int i = 0; i < 4; i++) acc[nt][i] = 0.0f;

    // A fragment LDS address pieces
    const int a_r  = warp * 16 + (lane >> 2);
    const int a_kb = (lane & 3) * 8;              // byte offset of k-pair
    const uint32_t brow8 = (uint32_t)(((lane >> 4) & 1) * 8 + (lane & 7));
    const uint32_t bkb   = (uint32_t)(((lane >> 3) & 1) * 16);

    for (int c = 0; c < NCHUNK; c++) {
        const int bi = c & 1;
        if (c + 1 < NCHUNK) {
            issueChunk(bi ^ 1, (c + 1) * KC_);
            asm volatile("cp.async.wait_group 1;");
        } else {
            asm volatile("cp.async.wait_group 0;");
        }
        __syncthreads();

        const char* abuf = smem + SM_ABUF + bi * A_STAGE;
        const uint32_t bbufa = sb + SM_BBUF + bi * B_STAGE;

#pragma unroll
        for (int ks = 0; ks < 4; ks++) {
            // ---- assemble A hi/lo fragments from fp32 smem ----
            const char* ap = abuf + a_r * A_ROWB + ks * 64 + a_kb;
            float2 v00 = *(const float2*)(ap);
            float2 v01 = *(const float2*)(ap + 32);
            float2 v10 = *(const float2*)(ap + 8 * A_ROWB);
            float2 v11 = *(const float2*)(ap + 8 * A_ROWB + 32);
            __half2 h00 = __floats2half2_rn(v00.x, v00.y);
            __half2 h10 = __floats2half2_rn(v10.x, v10.y);
            __half2 h01 = __floats2half2_rn(v01.x, v01.y);
            __half2 h11 = __floats2half2_rn(v11.x, v11.y);
            float2 f00 = __half22float2(h00), f10 = __half22float2(h10);
            float2 f01 = __half22float2(h01), f11 = __half22float2(h11);
            __half2 e00 = __floats2half2_rn(v00.x - f00.x, v00.y - f00.y);
            __half2 e10 = __floats2half2_rn(v10.x - f10.x, v10.y - f10.y);
            __half2 e01 = __floats2half2_rn(v01.x - f01.x, v01.y - f01.y);
            __half2 e11 = __floats2half2_rn(v11.x - f11.x, v11.y - f11.y);
            uint32_t ah[4] = { *(uint32_t*)&h00, *(uint32_t*)&h10,
                               *(uint32_t*)&h01, *(uint32_t*)&h11 };
            uint32_t al[4] = { *(uint32_t*)&e00, *(uint32_t*)&e10,
                               *(uint32_t*)&e01, *(uint32_t*)&e11 };

#pragma unroll
            for (int j = 0; j < 4; j++) {
                uint32_t bh[4], bl[4];
                uint32_t boff = sw128((uint32_t)(j * 16 + (int)brow8) * 128 +
                                      (uint32_t)(ks * 32) + bkb);
                ldmx4(bh, bbufa + boff);
                ldmx4(bl, bbufa + BLO_OFF + boff);
                mma16816(acc[2 * j],     ah, bh[0], bh[1]);
                mma16816(acc[2 * j],     ah, bl[0], bl[1]);
                mma16816(acc[2 * j],     al, bh[0], bh[1]);
                mma16816(acc[2 * j + 1], ah, bh[2], bh[3]);
                mma16816(acc[2 * j + 1], ah, bl[2], bl[3]);
                mma16816(acc[2 * j + 1], al, bh[2], bh[3]);
            }
        }
        __syncthreads();
    }

    // ---- epilogue: bias + ReLU -> e-tile (64 x 66, reuse A buffer) ----
    float* etile = (float*)(smem + SM_ABUF);
    {
        int r0 = warp * 16 + (lane >> 2);
        int cq = 2 * (lane & 3);
#pragma unroll
        for (int nt = 0; nt < 8; nt++) {
            int col = nt * 8 + cq;
            float bv0 = b1s[col], bv1 = b1s[col + 1];
            etile[r0 * 66 + col]           = fmaxf(acc[nt][0] + bv0, 0.0f);
            etile[r0 * 66 + col + 1]       = fmaxf(acc[nt][1] + bv1, 0.0f);
            etile[(r0 + 8) * 66 + col]     = fmaxf(acc[nt][2] + bv0, 0.0f);
            etile[(r0 + 8) * 66 + col + 1] = fmaxf(acc[nt][3] + bv1, 0.0f);
        }
    }
    __syncthreads();

    {   // split-row segment reduction: no atomics
        int half = tid >> 6;
        int e    = tid & 63;
        float* cs = csum + half * (CLN_ * EMB_);
        int rbase = half * 32;
        for (int r = 0; r < 32; r++) {
            int row = rbase + r;
            cs[labs[row] * EMB_ + e] += etile[row * 66 + e];
        }
    }
    __syncthreads();

    float* prow = g_part + ((size_t)b * NCTA_X + bx) * PSTRIDE;
    for (int i = tid; i < CLN_ * EMB_; i += NTHR)
        prow[i] = csum[i] + csum[CLN_ * EMB_ + i];
    if (tid < CLN_) {
        int cnt = 0;
        for (int r = 0; r < TILE_M; r++) cnt += (labs[r] == tid);
        prow[640 + tid] = (float)cnt;
    }
    __threadfence();
    __syncthreads();

    // ---- last CTA of this batch runs the head ----
    __shared__ int s_last;
    if (tid == 0) s_last = (atomicAdd(&g_done[b], 1) == NCTA_X - 1) ? 1 : 0;
    __syncthreads();
    if (!s_last) return;
    __threadfence();

    // head scratch in B-buffer region
    float* hc    = (float*)(smem + SM_BBUF);        // 650
    float* h     = hc + 656;                        // 640
    float* u     = h + 640;                         // 320
    float* score = u + 320;                         // 10
    float* Avec  = score + 16;                      // 10
    float* mask  = Avec + 16;                       // 10
    float* Mv    = mask + 16;                       // 64
    float* f     = Mv + 64;                         // 32

    for (int i = tid; i < 650; i += NTHR) {
        float s = 0.0f;
        const float* base = g_part + (size_t)b * NCTA_X * PSTRIDE + i;
#pragma unroll
        for (int j = 0; j < NCTA_X; j++) s += base[j * PSTRIDE];
        hc[i] = s;
    }
    __syncthreads();

    if (tid < EMB_) {
        for (int c = 0; c < CLN_; c++)
            h[c * EMB_ + tid] = hc[c * EMB_ + tid] / fmaxf(hc[640 + c], 1.0f);
    }
    if (tid < CLN_) mask[tid] = (hc[640 + tid] > 0.0f) ? 1.0f : 0.0f;
    __syncthreads();

    if (tid < 32) {
        for (int c = 0; c < CLN_; c++) {
            float s = ba1[tid];
            for (int e = 0; e < EMB_; e++) s += h[c * EMB_ + e] * Wa1[tid * EMB_ + e];
            u[c * 32 + tid] = tanhf(s);
        }
    }
    __syncthreads();

    if (tid < CLN_) {
        float s = ba2[0];
        for (int k = 0; k < 32; k++) s += u[tid * 32 + k] * Wa2[k];
        score[tid] = s;
    }
    __syncthreads();

    if (tid == 0) {
        float xmax = -1e30f;
        for (int c = 0; c < CLN_; c++) {
            float xm = score[c] * mask[c] + (1.0f - 1.0f / (mask[c] + 1e-5f));
            xmax = fmaxf(xmax, xm);
        }
        float ssum = 0.0f;
        for (int c = 0; c < CLN_; c++) {
            float ex = expf(score[c] - xmax) * mask[c];
            Avec[c] = ex;
            ssum += ex;
        }
        for (int c = 0; c < CLN_; c++) Avec[c] /= ssum;
    }
    __syncthreads();

    if (tid < EMB_) {
        float m = 0.0f;
        for (int c = 0; c < CLN_; c++) m += Avec[c] * h[c * EMB_ + tid];
        Mv[tid] = m;
    }
    __syncthreads();

    if (tid < 32) {
        float s = bf1[tid];
        for (int e = 0; e < EMB_; e++) s += Mv[e] * Wf1[tid * EMB_ + e];
        f[tid] = fmaxf(s, 0.0f);
    }
    __syncthreads();

    if (tid == 0) {
        float s = bf2[0];
        for (int k = 0; k < 32; k++) s += f[k] * Wf2[k];
        out[b] = s;
        g_done[b] = 0;      // reset for next graph replay
    }
}

// ---------------------------------------------------------------------------
extern "C" void kernel_launch(void* const* d_in, const int* in_sizes, int n_in,
                              void* d_out, int out_size) {
    const float* data   = (const float*)d_in[0];
    const int*   labels = (const int*)  d_in[1];
    const float* W1     = (const float*)d_in[2];
    const float* b1     = (const float*)d_in[3];
    const float* Wa1    = (const float*)d_in[4];
    const float* ba1    = (const float*)d_in[5];
    const float* Wa2    = (const float*)d_in[6];
    const float* ba2    = (const float*)d_in[7];
    const float* Wf1    = (const float*)d_in[8];
    const float* bf1    = (const float*)d_in[9];
    const float* Wf2    = (const float*)d_in[10];
    const float* bf2    = (const float*)d_in[11];

    cudaFuncSetAttribute(fused_kernel, cudaFuncAttributeMaxDynamicSharedMemorySize,
                         SMEM_TOTAL);

    init_kernel<<<64, 256>>>(W1);
    fused_kernel<<<dim3(NCTA_X, B_), NTHR, SMEM_TOTAL>>>(
        data, labels, b1, Wa1, ba1, Wa2, ba2, Wf1, bf1, Wf2, bf2,
        (float*)d_out);
}